// round 15
// baseline (speedup 1.0000x reference)
#include <cuda_runtime.h>
#include <cuda_bf16.h>
#include <math.h>
#include <stdint.h>

#define NN   50000
#define EE   800000
#define IND  128
#define HIDD 256
#define OUTD 40
#define TOT  (EE + NN)
#define XQ   (NN * IND / 4)     // x quads for bf16 cast
#define BN_EPS 1e-5f

// ---------------- scratch (device globals: alloc-guard compliant) ----------------
__device__ __align__(16) __nv_bfloat16 g_t1[(size_t)NN * HIDD];
__device__ __align__(16) __nv_bfloat16 g_t2[(size_t)NN * HIDD];
__device__ __align__(16) __nv_bfloat16 g_xb[(size_t)NN * IND];
__device__ float g_dinv[NN];
__device__ int   g_deg[NN];
__device__ int   g_cnt[NN];
__device__ int   g_cur[NN];
__device__ int   g_off[NN + 1];
__device__ int   g_row[EE];
__device__ int   g_col[EE];
__device__ __align__(16) int   g_csr_col[TOT + 4];
__device__ __align__(16) float g_csr_w[TOT + 4];
__device__ float g_sum[HIDD];     // zero-init at load; bn_finalize re-zeroes after use
__device__ float g_sumsq[HIDD];
__device__ float g_bn_s[HIDD];
__device__ float g_bn_t[HIDD];

static inline int cdiv(int a, int b) { return (a + b - 1) / b; }

// ---------------- tf32 helpers ----------------
__device__ __forceinline__ float to_tf32(float x) {
    uint32_t u;
    asm("cvt.rna.tf32.f32 %0, %1;" : "=r"(u) : "f"(x));
    return __uint_as_float(u);
}

__device__ __forceinline__ void mma_tf32(float c[4], const uint32_t a[4], const uint32_t b[2]) {
    asm volatile(
        "mma.sync.aligned.m16n8k8.row.col.f32.tf32.tf32.f32 "
        "{%0,%1,%2,%3}, {%4,%5,%6,%7}, {%8,%9}, {%0,%1,%2,%3};\n"
        : "+f"(c[0]), "+f"(c[1]), "+f"(c[2]), "+f"(c[3])
        : "r"(a[0]), "r"(a[1]), "r"(a[2]), "r"(a[3]), "r"(b[0]), "r"(b[1]));
}

// ---------------- preprocessing ----------------
__global__ void k_convert_deg_xcast(const void* ei, const float* __restrict__ x) {
    int idx = blockIdx.x * blockDim.x + threadIdx.x;
    if (idx < XQ) {
        float4 v = *reinterpret_cast<const float4*>(x + (size_t)idx * 4);
        __nv_bfloat162 a = __floats2bfloat162_rn(v.x, v.y);
        __nv_bfloat162 b = __floats2bfloat162_rn(v.z, v.w);
        uint2 u = make_uint2(*reinterpret_cast<uint32_t*>(&a),
                             *reinterpret_cast<uint32_t*>(&b));
        *reinterpret_cast<uint2*>(g_xb + (size_t)idx * 4) = u;
    }
    if (idx >= EE) return;
    const unsigned long long* p8 = (const unsigned long long*)ei;
    bool is64 = true;
#pragma unroll
    for (int q = 0; q < 8; q++) is64 &= (p8[q] < (unsigned long long)NN);
    int r, c;
    if (is64) {
        const long long* p = (const long long*)ei;
        r = (int)p[idx];
        c = (int)p[EE + idx];
    } else {
        const int* p = (const int*)ei;
        r = p[idx];
        c = p[EE + idx];
    }
    g_row[idx] = r;
    g_col[idx] = c;
    atomicAdd(&g_deg[c], 1);
    atomicAdd(&g_cnt[r], 1);
}

__global__ void k_scan_dinv() {
    __shared__ int part[1024];
    int t = threadIdx.x;
    const int CH = (NN + 1023) / 1024;
    int b = t * CH;
    int e = min(NN, b + CH);
    int s = 0;
    for (int i = b; i < e; i++) {
        s += g_cnt[i] + 1;
        g_dinv[i] = rsqrtf((float)(g_deg[i] + 1));
        g_deg[i] = 0;
        g_cur[i] = 0;
    }
    part[t] = s;
    __syncthreads();
    for (int off = 1; off < 1024; off <<= 1) {
        int v = (t >= off) ? part[t - off] : 0;
        __syncthreads();
        part[t] += v;
        __syncthreads();
    }
    int pre = (t == 0) ? 0 : part[t - 1];
    for (int i = b; i < e; i++) {
        g_off[i] = pre;
        pre += g_cnt[i] + 1;
        g_cnt[i] = 0;
    }
    if (t == 1023) g_off[NN] = part[1023];
}

__global__ void k_fill() {
    int idx = blockIdx.x * blockDim.x + threadIdx.x;
    if (idx >= TOT) return;
    int r, c; float w;
    if (idx < EE) {
        r = g_row[idx];
        c = g_col[idx];
        w = g_dinv[r] * g_dinv[c];
    } else {
        r = idx - EE;
        c = r;
        float d = g_dinv[r];
        w = d * d;
    }
    int pos = g_off[r] + atomicAdd(&g_cur[r], 1);
    g_csr_col[pos] = c;
    g_csr_w[pos]   = w;
}

// ---------------- tensor-core GEMM: bf16 A-in, tf32 mainloop, bf16 out ----------------
// __launch_bounds__(256, 3): force regs <= 85 so 3 CTAs/SM fit (occ 23% -> ~35%).
template <bool FUSE, bool BIAS, bool STATS>
__global__ void __launch_bounds__(256, 3) k_gemm_tc(
    const __nv_bfloat16* __restrict__ A, const float* __restrict__ B,
    const float* __restrict__ bias, __nv_bfloat16* __restrict__ C,
    int M, int K, int Ncols)
{
    constexpr int BM = 128, BN = 64, BK = 32;
    constexpr int ASTR = 36, BSTR = 68;
    __shared__ float As[BM * ASTR];
    __shared__ float Bs[BK * BSTR];

    const int tid  = threadIdx.x;
    const int warp = tid >> 5, lane = tid & 31;
    const int gid  = lane >> 2, tg = lane & 3;
    const int wm   = (warp & 3) * 32;
    const int wn   = (warp >> 2) * 32;
    const int bm   = blockIdx.y * BM, bn = blockIdx.x * BN;

    float c[2][4][4];
#pragma unroll
    for (int i = 0; i < 2; i++)
#pragma unroll
        for (int j = 0; j < 4; j++)
#pragma unroll
            for (int q = 0; q < 4; q++) c[i][j][q] = 0.f;

    uint4 areg[2];     // 8 bf16 per load
    float breg[8];

#pragma unroll
    for (int r = 0; r < 2; r++) {
        int idx = tid + r * 256;
        int m = idx >> 2, c8 = idx & 3;
        int gm = bm + m;
        areg[r] = make_uint4(0u, 0u, 0u, 0u);
        if (gm < M) areg[r] = *reinterpret_cast<const uint4*>(A + (size_t)gm * K + c8 * 8);
    }
#pragma unroll
    for (int r = 0; r < 8; r++) {
        int idx = tid + r * 256;
        int kk = idx >> 6, n = idx & 63;
        breg[r] = (bn + n < Ncols) ? B[(size_t)kk * Ncols + bn + n] : 0.f;
    }

    for (int k0 = 0; k0 < K; k0 += BK) {
#pragma unroll
        for (int r = 0; r < 2; r++) {
            int idx = tid + r * 256;
            int m = idx >> 2, c8 = idx & 3;
            const uint32_t* u = &areg[r].x;
            float f[8];
#pragma unroll
            for (int j = 0; j < 4; j++) {
                float2 p = __bfloat1622float2(
                    *reinterpret_cast<const __nv_bfloat162*>(&u[j]));
                f[2 * j] = p.x;
                f[2 * j + 1] = p.y;
            }
            if (FUSE) {
                int gk = k0 + c8 * 8;
#pragma unroll
                for (int j = 0; j < 8; j++)
                    f[j] = fmaxf(0.f, fmaf(f[j], g_bn_s[gk + j], g_bn_t[gk + j]));
            }
            *reinterpret_cast<float4*>(&As[m * ASTR + c8 * 8]) =
                make_float4(to_tf32(f[0]), to_tf32(f[1]), to_tf32(f[2]), to_tf32(f[3]));
            *reinterpret_cast<float4*>(&As[m * ASTR + c8 * 8 + 4]) =
                make_float4(to_tf32(f[4]), to_tf32(f[5]), to_tf32(f[6]), to_tf32(f[7]));
        }
#pragma unroll
        for (int r = 0; r < 8; r++) {
            int idx = tid + r * 256;
            int kk = idx >> 6, n = idx & 63;
            Bs[kk * BSTR + n] = to_tf32(breg[r]);
        }
        __syncthreads();

        if (k0 + BK < K) {
            int kn = k0 + BK;
#pragma unroll
            for (int r = 0; r < 2; r++) {
                int idx = tid + r * 256;
                int m = idx >> 2, c8 = idx & 3;
                int gm = bm + m;
                areg[r] = make_uint4(0u, 0u, 0u, 0u);
                if (gm < M) areg[r] = *reinterpret_cast<const uint4*>(A + (size_t)gm * K + kn + c8 * 8);
            }
#pragma unroll
            for (int r = 0; r < 8; r++) {
                int idx = tid + r * 256;
                int kk = idx >> 6, n = idx & 63;
                breg[r] = (bn + n < Ncols) ? B[(size_t)(kn + kk) * Ncols + bn + n] : 0.f;
            }
        }

#pragma unroll
        for (int kc = 0; kc < 4; kc++) {
            int kb = kc * 8 + tg;
            uint32_t a[2][4], b[4][2];
#pragma unroll
            for (int am = 0; am < 2; am++) {
                int mr = wm + am * 16 + gid;
                a[am][0] = __float_as_uint(As[mr * ASTR + kb]);
                a[am][1] = __float_as_uint(As[(mr + 8) * ASTR + kb]);
                a[am][2] = __float_as_uint(As[mr * ASTR + kb + 4]);
                a[am][3] = __float_as_uint(As[(mr + 8) * ASTR + kb + 4]);
            }
#pragma unroll
            for (int bi = 0; bi < 4; bi++) {
                int nc = wn + bi * 8 + gid;
                b[bi][0] = __float_as_uint(Bs[kb * BSTR + nc]);
                b[bi][1] = __float_as_uint(Bs[(kb + 4) * BSTR + nc]);
            }
#pragma unroll
            for (int am = 0; am < 2; am++)
#pragma unroll
                for (int bi = 0; bi < 4; bi++)
                    mma_tf32(c[am][bi], a[am], b[bi]);
        }
        __syncthreads();
    }

    float csum[4][2], csq[4][2];
    if (STATS) {
#pragma unroll
        for (int bi = 0; bi < 4; bi++) {
            csum[bi][0] = csum[bi][1] = 0.f;
            csq[bi][0] = csq[bi][1] = 0.f;
        }
    }
#pragma unroll
    for (int am = 0; am < 2; am++) {
#pragma unroll
        for (int bi = 0; bi < 4; bi++) {
            int row = bm + wm + am * 16 + gid;
            int col = bn + wn + bi * 8 + 2 * tg;
            float bv0 = 0.f, bv1 = 0.f;
            if (BIAS) {
                if (col < Ncols)     bv0 = bias[col];
                if (col + 1 < Ncols) bv1 = bias[col + 1];
            }
            float v0 = c[am][bi][0] + bv0, v1 = c[am][bi][1] + bv1;
            float v2 = c[am][bi][2] + bv0, v3 = c[am][bi][3] + bv1;
            if (row < M && col < Ncols)
                *reinterpret_cast<__nv_bfloat162*>(C + (size_t)row * Ncols + col) =
                    __floats2bfloat162_rn(v0, v1);
            if (row + 8 < M && col < Ncols)
                *reinterpret_cast<__nv_bfloat162*>(C + (size_t)(row + 8) * Ncols + col) =
                    __floats2bfloat162_rn(v2, v3);
            if (STATS) {
                if (row < M) {
                    csum[bi][0] += v0; csq[bi][0] = fmaf(v0, v0, csq[bi][0]);
                    csum[bi][1] += v1; csq[bi][1] = fmaf(v1, v1, csq[bi][1]);
                }
                if (row + 8 < M) {
                    csum[bi][0] += v2; csq[bi][0] = fmaf(v2, v2, csq[bi][0]);
                    csum[bi][1] += v3; csq[bi][1] = fmaf(v3, v3, csq[bi][1]);
                }
            }
        }
    }
    if (STATS) {
#pragma unroll
        for (int bi = 0; bi < 4; bi++) {
#pragma unroll
            for (int j = 0; j < 2; j++) {
                float s = csum[bi][j], q = csq[bi][j];
#pragma unroll
                for (int m = 4; m < 32; m <<= 1) {
                    s += __shfl_xor_sync(0xFFFFFFFFu, s, m);
                    q += __shfl_xor_sync(0xFFFFFFFFu, q, m);
                }
                if (gid == 0) {
                    int col = bn + wn + bi * 8 + 2 * tg + j;
                    if (col < Ncols) {
                        atomicAdd(&g_sum[col], s);
                        atomicAdd(&g_sumsq[col], q);
                    }
                }
            }
        }
    }
}

// ---------------- bf16 aggregation: gather bf16, fp32 accum, bf16 out (+stats) ----------------
template <int F, int RPB, bool BIAS, bool STATS>
__global__ void __launch_bounds__(32 * RPB) k_agg_bf16(
    const __nv_bfloat16* __restrict__ h, const float* __restrict__ bias,
    __nv_bfloat16* __restrict__ out)
{
    constexpr int V = F / 32;
    constexpr int V2 = V / 2;
    __shared__ float ssum[STATS ? F : 1];
    __shared__ float ssq[STATS ? F : 1];
    int i = blockIdx.x * RPB + threadIdx.x / 32;
    int t = threadIdx.x % 32;

    if (STATS) {
#pragma unroll
        for (int j = threadIdx.x; j < F; j += 32 * RPB) {
            ssum[j] = 0.f;
            ssq[j] = 0.f;
        }
        __syncthreads();
    }

    if (i < NN) {
        float acc[V];
#pragma unroll
        for (int j = 0; j < V; j++) acc[j] = 0.f;
        int p = g_off[i], end = g_off[i + 1];

#define GATHER_BF(cc, ww)                                                           \
    {                                                                               \
        uint32_t wreg[V2];                                                          \
        const __nv_bfloat16* src = h + (size_t)(cc) * F + t * V;                    \
        if constexpr (V2 == 2) {                                                    \
            uint2 u = *reinterpret_cast<const uint2*>(src);                         \
            wreg[0] = u.x; wreg[1] = u.y;                                           \
        } else {                                                                    \
            uint4 u = *reinterpret_cast<const uint4*>(src);                         \
            wreg[0] = u.x; wreg[1] = u.y; wreg[2] = u.z; wreg[3] = u.w;             \
        }                                                                           \
        _Pragma("unroll")                                                           \
        for (int j = 0; j < V2; j++) {                                              \
            float2 f = __bfloat1622float2(                                          \
                *reinterpret_cast<const __nv_bfloat162*>(&wreg[j]));                \
            acc[2 * j]     = fmaf((ww), f.x, acc[2 * j]);                           \
            acc[2 * j + 1] = fmaf((ww), f.y, acc[2 * j + 1]);                       \
        }                                                                           \
    }

        while (p < end && (p & 3)) {
            GATHER_BF(__ldg(&g_csr_col[p]), __ldg(&g_csr_w[p]));
            p++;
        }
        for (; p + 3 < end; p += 4) {
            int4   cv = *reinterpret_cast<const int4*>(&g_csr_col[p]);
            float4 wv = *reinterpret_cast<const float4*>(&g_csr_w[p]);
            GATHER_BF(cv.x, wv.x);
            GATHER_BF(cv.y, wv.y);
            GATHER_BF(cv.z, wv.z);
            GATHER_BF(cv.w, wv.w);
        }
        for (; p < end; p++) {
            GATHER_BF(__ldg(&g_csr_col[p]), __ldg(&g_csr_w[p]));
        }
#undef GATHER_BF

        uint32_t packed[V2];
#pragma unroll
        for (int j = 0; j < V; j++) {
            if (BIAS) acc[j] += bias[t * V + j];
            if (STATS) {
                atomicAdd(&ssum[t * V + j], acc[j]);
                atomicAdd(&ssq[t * V + j], acc[j] * acc[j]);
            }
        }
#pragma unroll
        for (int j = 0; j < V2; j++) {
            __nv_bfloat162 pb = __floats2bfloat162_rn(acc[2 * j], acc[2 * j + 1]);
            packed[j] = *reinterpret_cast<uint32_t*>(&pb);
        }
        __nv_bfloat16* dst = out + (size_t)i * F + t * V;
        if constexpr (V2 == 2) {
            *reinterpret_cast<uint2*>(dst) = make_uint2(packed[0], packed[1]);
        } else {
            *reinterpret_cast<uint4*>(dst) = make_uint4(packed[0], packed[1], packed[2], packed[3]);
        }
    }

    if (STATS) {
        __syncthreads();
#pragma unroll
        for (int j = threadIdx.x; j < F; j += 32 * RPB) {
            atomicAdd(&g_sum[j], ssum[j]);
            atomicAdd(&g_sumsq[j], ssq[j]);
        }
    }
}

// ---------------- fused layer-3 bf16 agg + log_softmax (warp per row) ----------------
__global__ void __launch_bounds__(128) k_agg_softmax_bf16(
    const __nv_bfloat16* __restrict__ h, const float* __restrict__ bias,
    float* __restrict__ out)
{
    int i = blockIdx.x * 4 + (threadIdx.x >> 5);
    int t = threadIdx.x & 31;
    if (i >= NN) return;
    float a0 = 0.f, a1 = 0.f;
    int p = g_off[i], end = g_off[i + 1];
    bool act = (t < OUTD / 2);
    for (; p + 1 < end; p += 2) {
        int   c0 = __ldg(&g_csr_col[p]);
        int   c1 = __ldg(&g_csr_col[p + 1]);
        float w0 = __ldg(&g_csr_w[p]);
        float w1 = __ldg(&g_csr_w[p + 1]);
        if (act) {
            float2 f0 = __bfloat1622float2(
                *reinterpret_cast<const __nv_bfloat162*>(h + (size_t)c0 * OUTD + 2 * t));
            float2 f1 = __bfloat1622float2(
                *reinterpret_cast<const __nv_bfloat162*>(h + (size_t)c1 * OUTD + 2 * t));
            a0 = fmaf(w0, f0.x, fmaf(w1, f1.x, a0));
            a1 = fmaf(w0, f0.y, fmaf(w1, f1.y, a1));
        }
    }
    if (p < end && act) {
        int   c0 = __ldg(&g_csr_col[p]);
        float w0 = __ldg(&g_csr_w[p]);
        float2 f0 = __bfloat1622float2(
            *reinterpret_cast<const __nv_bfloat162*>(h + (size_t)c0 * OUTD + 2 * t));
        a0 = fmaf(w0, f0.x, a0);
        a1 = fmaf(w0, f0.y, a1);
    }
    float v0 = act ? (a0 + bias[2 * t])     : -INFINITY;
    float v1 = act ? (a1 + bias[2 * t + 1]) : -INFINITY;
    float m = fmaxf(v0, v1);
#pragma unroll
    for (int off = 16; off > 0; off >>= 1)
        m = fmaxf(m, __shfl_xor_sync(0xFFFFFFFFu, m, off));
    float s = act ? (expf(v0 - m) + expf(v1 - m)) : 0.f;
#pragma unroll
    for (int off = 16; off > 0; off >>= 1)
        s += __shfl_xor_sync(0xFFFFFFFFu, s, off);
    float l = m + logf(s);
    if (act) {
        out[(size_t)i * OUTD + 2 * t]     = v0 - l;
        out[(size_t)i * OUTD + 2 * t + 1] = v1 - l;
    }
}

// ---------------- bn finalize (reads stats, re-zeroes for next pass) ----------------
__global__ void k_bn_finalize(const float* __restrict__ gamma,
                              const float* __restrict__ beta) {
    int c = threadIdx.x;
    float mu = g_sum[c] * (1.f / NN);
    float var = g_sumsq[c] * (1.f / NN) - mu * mu;
    float rstd = rsqrtf(var + BN_EPS);
    float sc = rstd * gamma[c];
    g_bn_s[c] = sc;
    g_bn_t[c] = beta[c] - mu * sc;
    g_sum[c] = 0.f;
    g_sumsq[c] = 0.f;
}

// ---------------- launch ----------------
extern "C" void kernel_launch(void* const* d_in, const int* in_sizes, int n_in,
                              void* d_out, int out_size) {
    const float* x     = (const float*)d_in[0];
    const void*  ei    = d_in[1];
    const float* W1    = (const float*)d_in[2];
    const float* b1    = (const float*)d_in[3];
    const float* W2    = (const float*)d_in[4];
    const float* b2    = (const float*)d_in[5];
    const float* W3    = (const float*)d_in[6];
    const float* b3    = (const float*)d_in[7];
    const float* gamma = (const float*)d_in[8];
    const float* beta  = (const float*)d_in[9];
    float* out = (float*)d_out;

    __nv_bfloat16 *t1, *t2, *xb;
    cudaGetSymbolAddress((void**)&t1, g_t1);
    cudaGetSymbolAddress((void**)&t2, g_t2);
    cudaGetSymbolAddress((void**)&xb, g_xb);

    // preprocessing
    k_convert_deg_xcast<<<cdiv(XQ, 256), 256>>>(ei, x);   // 0
    k_scan_dinv<<<1, 1024>>>();                           // 1
    k_fill<<<cdiv(TOT, 256), 256>>>();                    // 2

    dim3 g256(4, cdiv(NN, 128));    // Ncols=256
    dim3 g40(1, cdiv(NN, 128));     // Ncols=40

    // layer 1: bf16 agg (bf16 out), GEMM bf16-A with fused bias + BN stats, bf16 out
    k_agg_bf16<IND, 4, false, false><<<cdiv(NN, 4), 128>>>(xb, nullptr, t1);            // 3
    k_gemm_tc<false, true, true><<<g256, 256>>>(t1, W1, b1, t2, NN, IND, HIDD);         // 4
    k_bn_finalize<<<1, HIDD>>>(gamma, beta);                                            // 5

    // layer 2: GEMM bf16-A (BN+ReLU fused) -> bf16; agg bf16 -> bf16 + bias + stats
    k_gemm_tc<true, false, false><<<g256, 256>>>(t2, W2, nullptr, t1, NN, HIDD, HIDD);  // 6
    k_agg_bf16<HIDD, 4, true, true><<<cdiv(NN, 4), 128>>>(t1, b2, t2);                  // 7
    k_bn_finalize<<<1, HIDD>>>(gamma, beta);                                            // 8

    // layer 3: GEMM bf16-A (FUSE) -> bf16 logits; fused bf16 agg + log_softmax
    k_gemm_tc<true, false, false><<<g40, 256>>>(t2, W3, nullptr, t1, NN, HIDD, OUTD);   // 9
    k_agg_softmax_bf16<<<cdiv(NN, 4), 128>>>(t1, b3, out);                              // 10
}

// round 16
// speedup vs baseline: 1.1668x; 1.1668x over previous
#include <cuda_runtime.h>
#include <cuda_bf16.h>
#include <math.h>
#include <stdint.h>

#define NN   50000
#define EE   800000
#define IND  128
#define HIDD 256
#define OUTD 40
#define TOT  (EE + NN)
#define XQ   (NN * IND / 4)     // x quads for bf16 cast
#define BN_EPS 1e-5f

// ---------------- scratch (device globals: alloc-guard compliant) ----------------
__device__ __align__(16) __nv_bfloat16 g_t1[(size_t)NN * HIDD];
__device__ __align__(16) __nv_bfloat16 g_t2[(size_t)NN * HIDD];
__device__ __align__(16) __nv_bfloat16 g_xb[(size_t)NN * IND];
__device__ float g_dinv[NN];
__device__ int   g_deg[NN];
__device__ int   g_cnt[NN];
__device__ int   g_cur[NN];
__device__ int   g_off[NN + 1];
__device__ int   g_row[EE];
__device__ int   g_col[EE];
__device__ __align__(16) int   g_csr_col[TOT + 4];
__device__ __align__(16) float g_csr_w[TOT + 4];
__device__ float g_sum[HIDD];     // zero-init at load; bn_finalize re-zeroes after use
__device__ float g_sumsq[HIDD];
__device__ float g_bn_s[HIDD];
__device__ float g_bn_t[HIDD];

static inline int cdiv(int a, int b) { return (a + b - 1) / b; }

// ---------------- tf32 helpers ----------------
__device__ __forceinline__ float to_tf32(float x) {
    uint32_t u;
    asm("cvt.rna.tf32.f32 %0, %1;" : "=r"(u) : "f"(x));
    return __uint_as_float(u);
}

__device__ __forceinline__ void mma_tf32(float c[4], const uint32_t a[4], const uint32_t b[2]) {
    asm volatile(
        "mma.sync.aligned.m16n8k8.row.col.f32.tf32.tf32.f32 "
        "{%0,%1,%2,%3}, {%4,%5,%6,%7}, {%8,%9}, {%0,%1,%2,%3};\n"
        : "+f"(c[0]), "+f"(c[1]), "+f"(c[2]), "+f"(c[3])
        : "r"(a[0]), "r"(a[1]), "r"(a[2]), "r"(a[3]), "r"(b[0]), "r"(b[1]));
}

// ---------------- preprocessing ----------------
__global__ void k_convert_deg_xcast(const void* ei, const float* __restrict__ x) {
    int idx = blockIdx.x * blockDim.x + threadIdx.x;
    if (idx < XQ) {
        float4 v = *reinterpret_cast<const float4*>(x + (size_t)idx * 4);
        __nv_bfloat162 a = __floats2bfloat162_rn(v.x, v.y);
        __nv_bfloat162 b = __floats2bfloat162_rn(v.z, v.w);
        uint2 u = make_uint2(*reinterpret_cast<uint32_t*>(&a),
                             *reinterpret_cast<uint32_t*>(&b));
        *reinterpret_cast<uint2*>(g_xb + (size_t)idx * 4) = u;
    }
    if (idx >= EE) return;
    const unsigned long long* p8 = (const unsigned long long*)ei;
    bool is64 = true;
#pragma unroll
    for (int q = 0; q < 8; q++) is64 &= (p8[q] < (unsigned long long)NN);
    int r, c;
    if (is64) {
        const long long* p = (const long long*)ei;
        r = (int)p[idx];
        c = (int)p[EE + idx];
    } else {
        const int* p = (const int*)ei;
        r = p[idx];
        c = p[EE + idx];
    }
    g_row[idx] = r;
    g_col[idx] = c;
    atomicAdd(&g_deg[c], 1);
    atomicAdd(&g_cnt[r], 1);
}

__global__ void k_scan_dinv() {
    __shared__ int part[1024];
    int t = threadIdx.x;
    const int CH = (NN + 1023) / 1024;
    int b = t * CH;
    int e = min(NN, b + CH);
    int s = 0;
    for (int i = b; i < e; i++) {
        s += g_cnt[i] + 1;
        g_dinv[i] = rsqrtf((float)(g_deg[i] + 1));
        g_deg[i] = 0;
        g_cur[i] = 0;
    }
    part[t] = s;
    __syncthreads();
    for (int off = 1; off < 1024; off <<= 1) {
        int v = (t >= off) ? part[t - off] : 0;
        __syncthreads();
        part[t] += v;
        __syncthreads();
    }
    int pre = (t == 0) ? 0 : part[t - 1];
    for (int i = b; i < e; i++) {
        g_off[i] = pre;
        pre += g_cnt[i] + 1;
        g_cnt[i] = 0;
    }
    if (t == 1023) g_off[NN] = part[1023];
}

__global__ void k_fill() {
    int idx = blockIdx.x * blockDim.x + threadIdx.x;
    if (idx >= TOT) return;
    int r, c; float w;
    if (idx < EE) {
        r = g_row[idx];
        c = g_col[idx];
        w = g_dinv[r] * g_dinv[c];
    } else {
        r = idx - EE;
        c = r;
        float d = g_dinv[r];
        w = d * d;
    }
    int pos = g_off[r] + atomicAdd(&g_cur[r], 1);
    g_csr_col[pos] = c;
    g_csr_w[pos]   = w;
}

// ---------------- tensor-core GEMM: bf16 A-in, tf32 mainloop, bf16 out ----------------
template <bool FUSE, bool BIAS>
__global__ void __launch_bounds__(256, 3) k_gemm_tc(
    const __nv_bfloat16* __restrict__ A, const float* __restrict__ B,
    const float* __restrict__ bias, __nv_bfloat16* __restrict__ C,
    int M, int K, int Ncols)
{
    constexpr int BM = 128, BN = 64, BK = 32;
    constexpr int ASTR = 36, BSTR = 68;
    __shared__ float As[BM * ASTR];
    __shared__ float Bs[BK * BSTR];

    const int tid  = threadIdx.x;
    const int warp = tid >> 5, lane = tid & 31;
    const int gid  = lane >> 2, tg = lane & 3;
    const int wm   = (warp & 3) * 32;
    const int wn   = (warp >> 2) * 32;
    const int bm   = blockIdx.y * BM, bn = blockIdx.x * BN;

    float c[2][4][4];
#pragma unroll
    for (int i = 0; i < 2; i++)
#pragma unroll
        for (int j = 0; j < 4; j++)
#pragma unroll
            for (int q = 0; q < 4; q++) c[i][j][q] = 0.f;

    uint4 areg[2];     // 8 bf16 per load
    float breg[8];

#pragma unroll
    for (int r = 0; r < 2; r++) {
        int idx = tid + r * 256;
        int m = idx >> 2, c8 = idx & 3;
        int gm = bm + m;
        areg[r] = make_uint4(0u, 0u, 0u, 0u);
        if (gm < M) areg[r] = *reinterpret_cast<const uint4*>(A + (size_t)gm * K + c8 * 8);
    }
#pragma unroll
    for (int r = 0; r < 8; r++) {
        int idx = tid + r * 256;
        int kk = idx >> 6, n = idx & 63;
        breg[r] = (bn + n < Ncols) ? B[(size_t)kk * Ncols + bn + n] : 0.f;
    }

    for (int k0 = 0; k0 < K; k0 += BK) {
#pragma unroll
        for (int r = 0; r < 2; r++) {
            int idx = tid + r * 256;
            int m = idx >> 2, c8 = idx & 3;
            const uint32_t* u = &areg[r].x;
            float f[8];
#pragma unroll
            for (int j = 0; j < 4; j++) {
                float2 p = __bfloat1622float2(
                    *reinterpret_cast<const __nv_bfloat162*>(&u[j]));
                f[2 * j] = p.x;
                f[2 * j + 1] = p.y;
            }
            if (FUSE) {
                int gk = k0 + c8 * 8;
#pragma unroll
                for (int j = 0; j < 8; j++)
                    f[j] = fmaxf(0.f, fmaf(f[j], g_bn_s[gk + j], g_bn_t[gk + j]));
            }
            *reinterpret_cast<float4*>(&As[m * ASTR + c8 * 8]) =
                make_float4(to_tf32(f[0]), to_tf32(f[1]), to_tf32(f[2]), to_tf32(f[3]));
            *reinterpret_cast<float4*>(&As[m * ASTR + c8 * 8 + 4]) =
                make_float4(to_tf32(f[4]), to_tf32(f[5]), to_tf32(f[6]), to_tf32(f[7]));
        }
#pragma unroll
        for (int r = 0; r < 8; r++) {
            int idx = tid + r * 256;
            int kk = idx >> 6, n = idx & 63;
            Bs[kk * BSTR + n] = to_tf32(breg[r]);
        }
        __syncthreads();

        if (k0 + BK < K) {
            int kn = k0 + BK;
#pragma unroll
            for (int r = 0; r < 2; r++) {
                int idx = tid + r * 256;
                int m = idx >> 2, c8 = idx & 3;
                int gm = bm + m;
                areg[r] = make_uint4(0u, 0u, 0u, 0u);
                if (gm < M) areg[r] = *reinterpret_cast<const uint4*>(A + (size_t)gm * K + kn + c8 * 8);
            }
#pragma unroll
            for (int r = 0; r < 8; r++) {
                int idx = tid + r * 256;
                int kk = idx >> 6, n = idx & 63;
                breg[r] = (bn + n < Ncols) ? B[(size_t)(kn + kk) * Ncols + bn + n] : 0.f;
            }
        }

#pragma unroll
        for (int kc = 0; kc < 4; kc++) {
            int kb = kc * 8 + tg;
            uint32_t a[2][4], b[4][2];
#pragma unroll
            for (int am = 0; am < 2; am++) {
                int mr = wm + am * 16 + gid;
                a[am][0] = __float_as_uint(As[mr * ASTR + kb]);
                a[am][1] = __float_as_uint(As[(mr + 8) * ASTR + kb]);
                a[am][2] = __float_as_uint(As[mr * ASTR + kb + 4]);
                a[am][3] = __float_as_uint(As[(mr + 8) * ASTR + kb + 4]);
            }
#pragma unroll
            for (int bi = 0; bi < 4; bi++) {
                int nc = wn + bi * 8 + gid;
                b[bi][0] = __float_as_uint(Bs[kb * BSTR + nc]);
                b[bi][1] = __float_as_uint(Bs[(kb + 4) * BSTR + nc]);
            }
#pragma unroll
            for (int am = 0; am < 2; am++)
#pragma unroll
                for (int bi = 0; bi < 4; bi++)
                    mma_tf32(c[am][bi], a[am], b[bi]);
        }
        __syncthreads();
    }

#pragma unroll
    for (int am = 0; am < 2; am++) {
#pragma unroll
        for (int bi = 0; bi < 4; bi++) {
            int row = bm + wm + am * 16 + gid;
            int col = bn + wn + bi * 8 + 2 * tg;
            float bv0 = 0.f, bv1 = 0.f;
            if (BIAS) {
                if (col < Ncols)     bv0 = bias[col];
                if (col + 1 < Ncols) bv1 = bias[col + 1];
            }
            float v0 = c[am][bi][0] + bv0, v1 = c[am][bi][1] + bv1;
            float v2 = c[am][bi][2] + bv0, v3 = c[am][bi][3] + bv1;
            if (row < M && col < Ncols)
                *reinterpret_cast<__nv_bfloat162*>(C + (size_t)row * Ncols + col) =
                    __floats2bfloat162_rn(v0, v1);
            if (row + 8 < M && col < Ncols)
                *reinterpret_cast<__nv_bfloat162*>(C + (size_t)(row + 8) * Ncols + col) =
                    __floats2bfloat162_rn(v2, v3);
        }
    }
}

// ---------------- bf16 aggregation: gather bf16, fp32 accum, bf16 out ----------------
template <int F, int RPB, bool BIAS>
__global__ void __launch_bounds__(32 * RPB) k_agg_bf16(
    const __nv_bfloat16* __restrict__ h, const float* __restrict__ bias,
    __nv_bfloat16* __restrict__ out)
{
    constexpr int V = F / 32;
    constexpr int V2 = V / 2;
    int i = blockIdx.x * RPB + threadIdx.x / 32;
    int t = threadIdx.x % 32;
    if (i >= NN) return;
    float acc[V];
#pragma unroll
    for (int j = 0; j < V; j++) acc[j] = 0.f;
    int p = g_off[i], end = g_off[i + 1];

#define GATHER_BF(cc, ww)                                                           \
    {                                                                               \
        uint32_t wreg[V2];                                                          \
        const __nv_bfloat16* src = h + (size_t)(cc) * F + t * V;                    \
        if constexpr (V2 == 2) {                                                    \
            uint2 u = *reinterpret_cast<const uint2*>(src);                         \
            wreg[0] = u.x; wreg[1] = u.y;                                           \
        } else {                                                                    \
            uint4 u = *reinterpret_cast<const uint4*>(src);                         \
            wreg[0] = u.x; wreg[1] = u.y; wreg[2] = u.z; wreg[3] = u.w;             \
        }                                                                           \
        _Pragma("unroll")                                                           \
        for (int j = 0; j < V2; j++) {                                              \
            float2 f = __bfloat1622float2(                                          \
                *reinterpret_cast<const __nv_bfloat162*>(&wreg[j]));                \
            acc[2 * j]     = fmaf((ww), f.x, acc[2 * j]);                           \
            acc[2 * j + 1] = fmaf((ww), f.y, acc[2 * j + 1]);                       \
        }                                                                           \
    }

    while (p < end && (p & 3)) {
        GATHER_BF(__ldg(&g_csr_col[p]), __ldg(&g_csr_w[p]));
        p++;
    }
    for (; p + 3 < end; p += 4) {
        int4   cv = *reinterpret_cast<const int4*>(&g_csr_col[p]);
        float4 wv = *reinterpret_cast<const float4*>(&g_csr_w[p]);
        GATHER_BF(cv.x, wv.x);
        GATHER_BF(cv.y, wv.y);
        GATHER_BF(cv.z, wv.z);
        GATHER_BF(cv.w, wv.w);
    }
    for (; p < end; p++) {
        GATHER_BF(__ldg(&g_csr_col[p]), __ldg(&g_csr_w[p]));
    }
#undef GATHER_BF

    uint32_t packed[V2];
#pragma unroll
    for (int j = 0; j < V; j++)
        if (BIAS) acc[j] += bias[t * V + j];
#pragma unroll
    for (int j = 0; j < V2; j++) {
        __nv_bfloat162 pb = __floats2bfloat162_rn(acc[2 * j], acc[2 * j + 1]);
        packed[j] = *reinterpret_cast<uint32_t*>(&pb);
    }
    __nv_bfloat16* dst = out + (size_t)i * F + t * V;
    if constexpr (V2 == 2) {
        *reinterpret_cast<uint2*>(dst) = make_uint2(packed[0], packed[1]);
    } else {
        *reinterpret_cast<uint4*>(dst) = make_uint4(packed[0], packed[1], packed[2], packed[3]);
    }
}

// ---------------- bf16 batchnorm stats (column sums over bf16 matrix) ----------------
__global__ void __launch_bounds__(256) k_stats_bf16(const __nv_bfloat16* __restrict__ h) {
    int c2 = threadIdx.x;   // owns columns 2*c2, 2*c2+1 ... wait: 256 threads, 128 bf16x2 pairs
    // Each thread owns one bf16x2 pair (2 columns): tid 0..127. tid>=128 handles second half rows.
    // Simpler: 256 threads = 128 pairs x 2 row-groups.
    int pair = c2 & 127;          // column pair index 0..127
    int half = c2 >> 7;           // 0 or 1: row range split
    int rows_per_block = (NN + gridDim.x - 1) / gridDim.x;
    int r0 = blockIdx.x * rows_per_block + half * (rows_per_block / 2);
    int r1 = min(NN, (half ? blockIdx.x * rows_per_block + rows_per_block
                           : blockIdx.x * rows_per_block + rows_per_block / 2));
    float s0 = 0.f, s1 = 0.f, q0 = 0.f, q1 = 0.f;
    for (int r = r0; r < r1; r++) {
        float2 f = __bfloat1622float2(
            *reinterpret_cast<const __nv_bfloat162*>(h + (size_t)r * HIDD + pair * 2));
        s0 += f.x; q0 = fmaf(f.x, f.x, q0);
        s1 += f.y; q1 = fmaf(f.y, f.y, q1);
    }
    atomicAdd(&g_sum[pair * 2 + 0], s0); atomicAdd(&g_sumsq[pair * 2 + 0], q0);
    atomicAdd(&g_sum[pair * 2 + 1], s1); atomicAdd(&g_sumsq[pair * 2 + 1], q1);
}

// ---------------- fused layer-3 bf16 agg + log_softmax (warp per row) ----------------
__global__ void __launch_bounds__(128) k_agg_softmax_bf16(
    const __nv_bfloat16* __restrict__ h, const float* __restrict__ bias,
    float* __restrict__ out)
{
    int i = blockIdx.x * 4 + (threadIdx.x >> 5);
    int t = threadIdx.x & 31;
    if (i >= NN) return;
    float a0 = 0.f, a1 = 0.f;
    int p = g_off[i], end = g_off[i + 1];
    bool act = (t < OUTD / 2);
    for (; p + 1 < end; p += 2) {
        int   c0 = __ldg(&g_csr_col[p]);
        int   c1 = __ldg(&g_csr_col[p + 1]);
        float w0 = __ldg(&g_csr_w[p]);
        float w1 = __ldg(&g_csr_w[p + 1]);
        if (act) {
            float2 f0 = __bfloat1622float2(
                *reinterpret_cast<const __nv_bfloat162*>(h + (size_t)c0 * OUTD + 2 * t));
            float2 f1 = __bfloat1622float2(
                *reinterpret_cast<const __nv_bfloat162*>(h + (size_t)c1 * OUTD + 2 * t));
            a0 = fmaf(w0, f0.x, fmaf(w1, f1.x, a0));
            a1 = fmaf(w0, f0.y, fmaf(w1, f1.y, a1));
        }
    }
    if (p < end && act) {
        int   c0 = __ldg(&g_csr_col[p]);
        float w0 = __ldg(&g_csr_w[p]);
        float2 f0 = __bfloat1622float2(
            *reinterpret_cast<const __nv_bfloat162*>(h + (size_t)c0 * OUTD + 2 * t));
        a0 = fmaf(w0, f0.x, a0);
        a1 = fmaf(w0, f0.y, a1);
    }
    float v0 = act ? (a0 + bias[2 * t])     : -INFINITY;
    float v1 = act ? (a1 + bias[2 * t + 1]) : -INFINITY;
    float m = fmaxf(v0, v1);
#pragma unroll
    for (int off = 16; off > 0; off >>= 1)
        m = fmaxf(m, __shfl_xor_sync(0xFFFFFFFFu, m, off));
    float s = act ? (expf(v0 - m) + expf(v1 - m)) : 0.f;
#pragma unroll
    for (int off = 16; off > 0; off >>= 1)
        s += __shfl_xor_sync(0xFFFFFFFFu, s, off);
    float l = m + logf(s);
    if (act) {
        out[(size_t)i * OUTD + 2 * t]     = v0 - l;
        out[(size_t)i * OUTD + 2 * t + 1] = v1 - l;
    }
}

// ---------------- bn finalize (reads stats, re-zeroes for next pass) ----------------
__global__ void k_bn_finalize(const float* __restrict__ gamma,
                              const float* __restrict__ beta) {
    int c = threadIdx.x;
    float mu = g_sum[c] * (1.f / NN);
    float var = g_sumsq[c] * (1.f / NN) - mu * mu;
    float rstd = rsqrtf(var + BN_EPS);
    float sc = rstd * gamma[c];
    g_bn_s[c] = sc;
    g_bn_t[c] = beta[c] - mu * sc;
    g_sum[c] = 0.f;
    g_sumsq[c] = 0.f;
}

// ---------------- launch ----------------
extern "C" void kernel_launch(void* const* d_in, const int* in_sizes, int n_in,
                              void* d_out, int out_size) {
    const float* x     = (const float*)d_in[0];
    const void*  ei    = d_in[1];
    const float* W1    = (const float*)d_in[2];
    const float* b1    = (const float*)d_in[3];
    const float* W2    = (const float*)d_in[4];
    const float* b2    = (const float*)d_in[5];
    const float* W3    = (const float*)d_in[6];
    const float* b3    = (const float*)d_in[7];
    const float* gamma = (const float*)d_in[8];
    const float* beta  = (const float*)d_in[9];
    float* out = (float*)d_out;

    __nv_bfloat16 *t1, *t2, *xb;
    cudaGetSymbolAddress((void**)&t1, g_t1);
    cudaGetSymbolAddress((void**)&t2, g_t2);
    cudaGetSymbolAddress((void**)&xb, g_xb);

    // preprocessing
    k_convert_deg_xcast<<<cdiv(XQ, 256), 256>>>(ei, x);   // 0
    k_scan_dinv<<<1, 1024>>>();                           // 1
    k_fill<<<cdiv(TOT, 256), 256>>>();                    // 2

    dim3 g256(4, cdiv(NN, 128));    // Ncols=256
    dim3 g40(1, cdiv(NN, 128));     // Ncols=40

    // layer 1: bf16 agg (bf16 out), GEMM bf16-A (fused bias) -> bf16, standalone stats
    k_agg_bf16<IND, 4, false><<<cdiv(NN, 4), 128>>>(xb, nullptr, t1);            // 3
    k_gemm_tc<false, true><<<g256, 256>>>(t1, W1, b1, t2, NN, IND, HIDD);        // 4
    k_stats_bf16<<<256, 256>>>(t2);                                              // 5
    k_bn_finalize<<<1, HIDD>>>(gamma, beta);                                     // 6

    // layer 2: GEMM bf16-A (BN+ReLU fused) -> bf16; agg bf16 -> bf16 + bias; stats
    k_gemm_tc<true, false><<<g256, 256>>>(t2, W2, nullptr, t1, NN, HIDD, HIDD);  // 7
    k_agg_bf16<HIDD, 4, true><<<cdiv(NN, 4), 128>>>(t1, b2, t2);                 // 8
    k_stats_bf16<<<256, 256>>>(t2);                                              // 9
    k_bn_finalize<<<1, HIDD>>>(gamma, beta);                                     // 10

    // layer 3: GEMM bf16-A (FUSE) -> bf16 logits; fused bf16 agg + log_softmax
    k_gemm_tc<true, false><<<g40, 256>>>(t2, W3, nullptr, t1, NN, HIDD, OUTD);   // 11
    k_agg_softmax_bf16<<<cdiv(NN, 4), 128>>>(t1, b3, out);                       // 12
}